// round 1
// baseline (speedup 1.0000x reference)
#include <cuda_runtime.h>
#include <cstddef>

#define NN 40000
#define EE 640000
#define GG 1000
#define HC 128
#define NH 8
#define CC 16
#define MM 256

// ---------------- scratch (static device globals; no allocation) ----------------
__device__ float g_h[NN * HC];      // pre-aggregation features of current layer
__device__ float g_feat0[NN * HC];  // ping
__device__ float g_feat1[NN * HC];  // pong
__device__ float g_als[NN * NH];
__device__ float g_ald[NN * NH];
__device__ int   g_deg[NN];
__device__ int   g_cur[NN];
__device__ int   g_off[NN + 1];
__device__ int   g_csr[EE];
__device__ float g_pool[GG * HC];
__device__ float g_m0[GG * MM];
__device__ float g_m1[GG * MM];

__device__ __forceinline__ float lrelu(float x) { return x > 0.f ? x : 0.2f * x; }

// ---------------- CSR build ----------------
__global__ void k_zero() {
    int i = blockIdx.x * blockDim.x + threadIdx.x;
    if (i < NN) { g_deg[i] = 0; g_cur[i] = 0; }
}

__global__ void k_hist(const int* __restrict__ dst) {
    int i = blockIdx.x * blockDim.x + threadIdx.x;
    if (i < EE) atomicAdd(&g_deg[dst[i]], 1);
}

// single-block exclusive scan over g_deg -> g_off  (1024 threads, 40 items each)
__global__ void k_scan() {
    const int ITEMS = 40;  // 1024*40 = 40960 >= NN
    int t = threadIdx.x;
    int base = t * ITEMS;
    int sum = 0;
    for (int i = 0; i < ITEMS; i++) {
        int idx = base + i;
        if (idx < NN) sum += g_deg[idx];
    }
    __shared__ int wsum[32];
    int lane = t & 31, wid = t >> 5;
    int v = sum;
    #pragma unroll
    for (int o = 1; o < 32; o <<= 1) {
        int u = __shfl_up_sync(0xffffffffu, v, o);
        if (lane >= o) v += u;
    }
    if (lane == 31) wsum[wid] = v;
    __syncthreads();
    if (wid == 0) {
        int w = wsum[lane];
        #pragma unroll
        for (int o = 1; o < 32; o <<= 1) {
            int u = __shfl_up_sync(0xffffffffu, w, o);
            if (lane >= o) w += u;
        }
        wsum[lane] = w;
    }
    __syncthreads();
    int excl = v - sum + (wid > 0 ? wsum[wid - 1] : 0);
    int run = excl;
    for (int i = 0; i < ITEMS; i++) {
        int idx = base + i;
        if (idx < NN) { g_off[idx] = run; run += g_deg[idx]; }
    }
    if (t == 1023) g_off[NN] = EE;
}

__global__ void k_fill(const int* __restrict__ src, const int* __restrict__ dst) {
    int i = blockIdx.x * blockDim.x + threadIdx.x;
    if (i < EE) {
        int d = dst[i];
        int p = atomicAdd(&g_cur[d], 1);
        g_csr[g_off[d] + p] = src[i];
    }
}

// ---------------- node GEMM: out[N,128] = in[N,K] @ W[K,128] ----------------
// BM=64, BN=128, BK=32, 128 threads, 8x8 microtile.  grid = N/64 = 625.
template <int K>
__global__ void k_gemm(const float* __restrict__ in, const float* __restrict__ W,
                       float* __restrict__ out) {
    __shared__ float As[64][33];
    __shared__ __align__(16) float Bs[32][128];
    int t = threadIdx.x;
    int tc = t & 15;   // col group: cols tc*8 .. tc*8+7
    int tr = t >> 4;   // row group: rows tr*8 .. tr*8+7
    int row0 = blockIdx.x * 64;

    float acc[8][8];
    #pragma unroll
    for (int i = 0; i < 8; i++)
        #pragma unroll
        for (int j = 0; j < 8; j++) acc[i][j] = 0.f;

    for (int k0 = 0; k0 < K; k0 += 32) {
        #pragma unroll
        for (int it = 0; it < 4; it++) {
            int idx = t + it * 128;           // 0..511 float4 slots
            int r = idx >> 3;
            int k4 = (idx & 7) << 2;
            float4 v = *(const float4*)(in + (size_t)(row0 + r) * K + k0 + k4);
            As[r][k4 + 0] = v.x; As[r][k4 + 1] = v.y;
            As[r][k4 + 2] = v.z; As[r][k4 + 3] = v.w;
        }
        #pragma unroll
        for (int it = 0; it < 8; it++) {
            int idx = t + it * 128;           // 0..1023 float4 slots
            int kk = idx >> 5;
            int c4 = (idx & 31) << 2;
            *(float4*)&Bs[kk][c4] = *(const float4*)(W + (size_t)(k0 + kk) * 128 + c4);
        }
        __syncthreads();
        #pragma unroll 4
        for (int kk = 0; kk < 32; kk++) {
            float a[8];
            #pragma unroll
            for (int i = 0; i < 8; i++) a[i] = As[tr * 8 + i][kk];
            float4 b0 = *(const float4*)&Bs[kk][tc * 8];
            float4 b1 = *(const float4*)&Bs[kk][tc * 8 + 4];
            float b[8] = {b0.x, b0.y, b0.z, b0.w, b1.x, b1.y, b1.z, b1.w};
            #pragma unroll
            for (int i = 0; i < 8; i++)
                #pragma unroll
                for (int j = 0; j < 8; j++) acc[i][j] += a[i] * b[j];
        }
        __syncthreads();
    }
    #pragma unroll
    for (int i = 0; i < 8; i++) {
        float4 o0 = {acc[i][0], acc[i][1], acc[i][2], acc[i][3]};
        float4 o1 = {acc[i][4], acc[i][5], acc[i][6], acc[i][7]};
        float* p = out + (size_t)(row0 + tr * 8 + i) * 128 + tc * 8;
        *(float4*)p = o0;
        *(float4*)(p + 4) = o1;
    }
}

// ---------------- attention logits: als/ald [N, 8] ----------------
__global__ void k_logits(const float* __restrict__ h, const float* __restrict__ as_,
                         const float* __restrict__ ad_) {
    int tid = blockIdx.x * blockDim.x + threadIdx.x;
    if (tid >= NN * NH) return;
    int n = tid >> 3, hd = tid & 7;
    const float* hp = h + (size_t)n * HC + hd * CC;
    float s = 0.f, d2 = 0.f;
    #pragma unroll
    for (int c = 0; c < CC; c++) {
        float v = hp[c];
        s += v * as_[hd * CC + c];
        d2 += v * ad_[hd * CC + c];
    }
    g_als[tid] = s;
    g_ald[tid] = d2;
}

// ---------------- per-dst-node softmax + aggregation (warp per node) ----------------
__global__ void k_agg(const float* __restrict__ h, const float* __restrict__ bias,
                      float* __restrict__ out) {
    int warp = (blockIdx.x * blockDim.x + threadIdx.x) >> 5;
    if (warp >= NN) return;
    int lane = threadIdx.x & 31;
    int node = warp;
    int beg = g_off[node], end = g_off[node + 1];

    int head = lane & 7, sub = lane >> 3;        // 4 edge slots x 8 heads
    float aldh = g_ald[node * NH + head];
    float sself = g_als[node * NH + head];

    // pass 1: max of raw src logits (leaky-relu is monotone)
    float m = sself;  // self loop
    for (int e = beg + sub; e < end; e += 4)
        m = fmaxf(m, g_als[g_csr[e] * NH + head]);
    m = fmaxf(m, __shfl_xor_sync(0xffffffffu, m, 8));
    m = fmaxf(m, __shfl_xor_sync(0xffffffffu, m, 16));
    float emax = lrelu(m + aldh);

    // pass 2: softmax denominator
    float dsum = (sub == 0) ? __expf(lrelu(sself + aldh) - emax) : 0.f;
    for (int e = beg + sub; e < end; e += 4)
        dsum += __expf(lrelu(g_als[g_csr[e] * NH + head] + aldh) - emax);
    dsum += __shfl_xor_sync(0xffffffffu, dsum, 8);
    dsum += __shfl_xor_sync(0xffffffffu, dsum, 16);
    float inv = 1.f / dsum;

    // re-map: lane covers channels lane*4..lane*4+3, head3 = lane>>2
    int head3 = lane >> 2;
    float emax3 = __shfl_sync(0xffffffffu, emax, head3);  // lanes 0..7 hold heads 0..7
    float inv3  = __shfl_sync(0xffffffffu, inv,  head3);
    float ald3  = __shfl_sync(0xffffffffu, aldh, head3);

    // pass 3: weighted gather (self + edges)
    float4 acc;
    {
        float a = __expf(lrelu(g_als[node * NH + head3] + ald3) - emax3) * inv3;
        float4 hv = *(const float4*)(h + (size_t)node * HC + lane * 4);
        acc.x = a * hv.x; acc.y = a * hv.y; acc.z = a * hv.z; acc.w = a * hv.w;
    }
    for (int e = beg; e < end; e++) {
        int s = g_csr[e];
        float a = __expf(lrelu(g_als[s * NH + head3] + ald3) - emax3) * inv3;
        float4 hv = *(const float4*)(h + (size_t)s * HC + lane * 4);
        acc.x += a * hv.x; acc.y += a * hv.y; acc.z += a * hv.z; acc.w += a * hv.w;
    }
    float4 bv = *(const float4*)(bias + lane * 4);
    float4 o;
    o.x = fmaxf(acc.x + bv.x, 0.f);
    o.y = fmaxf(acc.y + bv.y, 0.f);
    o.z = fmaxf(acc.z + bv.z, 0.f);
    o.w = fmaxf(acc.w + bv.w, 0.f);
    *(float4*)(out + (size_t)node * HC + lane * 4) = o;
}

// ---------------- global mean pool (warp per graph; batch is sorted) ----------------
__device__ __forceinline__ int lower_bound_i(const int* __restrict__ a, int n, int key) {
    int lo = 0, hi = n;
    while (lo < hi) {
        int mid = (lo + hi) >> 1;
        if (a[mid] < key) lo = mid + 1; else hi = mid;
    }
    return lo;
}

__global__ void k_pool(const float* __restrict__ feat, const int* __restrict__ batch) {
    int warp = (blockIdx.x * blockDim.x + threadIdx.x) >> 5;
    if (warp >= GG) return;
    int lane = threadIdx.x & 31;
    int g = warp;
    int start = lower_bound_i(batch, NN, g);
    int end = lower_bound_i(batch, NN, g + 1);
    float4 acc = {0.f, 0.f, 0.f, 0.f};
    for (int n = start; n < end; n++) {
        float4 v = *(const float4*)(feat + (size_t)n * HC + lane * 4);
        acc.x += v.x; acc.y += v.y; acc.z += v.z; acc.w += v.w;
    }
    float invc = (end > start) ? 1.f / (float)(end - start) : 0.f;
    float4 o = {acc.x * invc, acc.y * invc, acc.z * invc, acc.w * invc};
    *(float4*)(g_pool + (size_t)g * HC + lane * 4) = o;
}

// ---------------- MLP fc layer (8 graphs per 256-thread block, Mo = 256) ----------------
template <int K>
__global__ void k_fc(const float* __restrict__ in, const float* __restrict__ W,
                     const float* __restrict__ b, float* __restrict__ out) {
    __shared__ float sin_[8 * 256];
    int g0 = blockIdx.x * 8;
    int t = threadIdx.x;  // output channel m
    for (int i = t; i < 8 * K; i += 256) sin_[i] = in[(size_t)g0 * K + i];
    __syncthreads();
    float acc[8] = {0, 0, 0, 0, 0, 0, 0, 0};
    for (int k = 0; k < K; k++) {
        float w = W[(size_t)k * MM + t];
        #pragma unroll
        for (int j = 0; j < 8; j++) acc[j] += sin_[j * K + k] * w;
    }
    float bb = b[t];
    #pragma unroll
    for (int j = 0; j < 8; j++)
        out[(size_t)(g0 + j) * MM + t] = fmaxf(acc[j] + bb, 0.f);
}

// ---------------- output head (warp per graph) ----------------
__global__ void k_head(const float* __restrict__ in, const float* __restrict__ oW,
                       const float* __restrict__ ob, float* __restrict__ out) {
    int warp = (blockIdx.x * blockDim.x + threadIdx.x) >> 5;
    if (warp >= GG) return;
    int lane = threadIdx.x & 31;
    const float* r = in + (size_t)warp * MM;
    float a0 = 0.f, a1 = 0.f;
    for (int k = lane; k < MM; k += 32) {
        float v = r[k];
        a0 += v * oW[k * 2];
        a1 += v * oW[k * 2 + 1];
    }
    #pragma unroll
    for (int o = 16; o > 0; o >>= 1) {
        a0 += __shfl_xor_sync(0xffffffffu, a0, o);
        a1 += __shfl_xor_sync(0xffffffffu, a1, o);
    }
    if (lane == 0) {
        out[warp * 2] = a0 + ob[0];
        out[warp * 2 + 1] = a1 + ob[1];
    }
}

// ---------------- launch ----------------
extern "C" void kernel_launch(void* const* d_in, const int* in_sizes, int n_in,
                              void* d_out, int out_size) {
    const float* x     = (const float*)d_in[0];
    const int*   ei    = (const int*)d_in[1];
    const int*   batch = (const int*)d_in[2];
    const float* W0  = (const float*)d_in[3];
    const float* b0  = (const float*)d_in[4];
    const float* as0 = (const float*)d_in[5];
    const float* ad0 = (const float*)d_in[6];
    const float* W1  = (const float*)d_in[7];
    const float* b1  = (const float*)d_in[8];
    const float* as1 = (const float*)d_in[9];
    const float* ad1 = (const float*)d_in[10];
    const float* W2  = (const float*)d_in[11];
    const float* b2  = (const float*)d_in[12];
    const float* as2 = (const float*)d_in[13];
    const float* ad2 = (const float*)d_in[14];
    const float* fW0 = (const float*)d_in[15];
    const float* fb0 = (const float*)d_in[16];
    const float* fW1 = (const float*)d_in[17];
    const float* fb1 = (const float*)d_in[18];
    const float* oW  = (const float*)d_in[19];
    const float* ob  = (const float*)d_in[20];
    float* out = (float*)d_out;

    const int* src = ei;
    const int* dst = ei + EE;

    float *p_h, *p_f0, *p_f1;
    cudaGetSymbolAddress((void**)&p_h,  g_h);
    cudaGetSymbolAddress((void**)&p_f0, g_feat0);
    cudaGetSymbolAddress((void**)&p_f1, g_feat1);
    float *p_pool, *p_m0, *p_m1;
    cudaGetSymbolAddress((void**)&p_pool, g_pool);
    cudaGetSymbolAddress((void**)&p_m0, g_m0);
    cudaGetSymbolAddress((void**)&p_m1, g_m1);

    // CSR build (per call; deterministic)
    k_zero<<<(NN + 255) / 256, 256>>>();
    k_hist<<<(EE + 255) / 256, 256>>>(dst);
    k_scan<<<1, 1024>>>();
    k_fill<<<(EE + 255) / 256, 256>>>(src, dst);

    const int GEMM_GRID = NN / 64;          // 625
    const int LOGITS_GRID = (NN * NH + 255) / 256;
    const int AGG_GRID = (NN + 7) / 8;      // 8 warps / 256-thread block

    // layer 0
    k_gemm<32><<<GEMM_GRID, 128>>>(x, W0, p_h);
    k_logits<<<LOGITS_GRID, 256>>>(p_h, as0, ad0);
    k_agg<<<AGG_GRID, 256>>>(p_h, b0, p_f0);
    // layer 1
    k_gemm<128><<<GEMM_GRID, 128>>>(p_f0, W1, p_h);
    k_logits<<<LOGITS_GRID, 256>>>(p_h, as1, ad1);
    k_agg<<<AGG_GRID, 256>>>(p_h, b1, p_f1);
    // layer 2
    k_gemm<128><<<GEMM_GRID, 128>>>(p_f1, W2, p_h);
    k_logits<<<LOGITS_GRID, 256>>>(p_h, as2, ad2);
    k_agg<<<AGG_GRID, 256>>>(p_h, b2, p_f0);

    // pool + MLP head
    k_pool<<<(GG * 32 + 255) / 256, 256>>>(p_f0, batch);
    k_fc<128><<<GG / 8, 256>>>(p_pool, fW0, fb0, p_m0);
    k_fc<256><<<GG / 8, 256>>>(p_m0, fW1, fb1, p_m1);
    k_head<<<(GG * 32 + 255) / 256, 256>>>(p_m1, oW, ob, out);
}